// round 15
// baseline (speedup 1.0000x reference)
#include <cuda_runtime.h>
#include <cstdint>

// ---------------- problem constants ----------------
#define B_    16
#define C_    128
#define T_    16384
#define W_    2048      // wordnum = T/patch
#define P_    8
#define MIDC_ 128
#define CP_   1024      // MIDC * P

// ---------------- scratch (device globals; allocation-free rule) ----------------
__device__ float    g_qr [(size_t)B_ * W_ * CP_];   // raw Q (pre-softmax) [b][w][i]
__device__ float    g_kt [(size_t)B_ * CP_ * W_];   // raw K^T (pre-softmax) [b][i][w]
__device__ uint16_t g_qh [(size_t)B_ * W_ * CP_];   // bf16 softmaxed Q    [b][w][i]
__device__ uint16_t g_kth[(size_t)B_ * CP_ * W_];   // bf16 softmax(K)^T   [b][i][w]
__device__ uint16_t g_vth[(size_t)B_ * CP_ * W_];   // bf16 V^T            [b][i][w]
__device__ uint16_t g_kvh[(size_t)B_ * CP_ * CP_];  // bf16 kv_mat^T       [b][i][j]
__device__ float    g_at [(size_t)B_ * MIDC_ * T_]; // attn out fp32       [b][m][t]

// ---------------- helpers ----------------
__device__ __forceinline__ uint32_t smem_u32(const void* p) {
    uint32_t a;
    asm("{ .reg .u64 t; cvta.to.shared.u64 t, %1; cvt.u32.u64 %0, t; }"
        : "=r"(a) : "l"(p));
    return a;
}

__device__ __forceinline__ float to_tf32(float x) {
    uint32_t u;
    asm("cvt.rna.tf32.f32 %0, %1;" : "=r"(u) : "f"(x));
    return __uint_as_float(u);
}

// pack two floats -> bf16x2 (lo = first arg)
__device__ __forceinline__ uint32_t pack_bf16(float lo, float hi) {
    uint32_t r;
    asm("cvt.rn.bf16x2.f32 %0, %1, %2;" : "=r"(r) : "f"(hi), "f"(lo));
    return r;
}

#define LDSM4(r, addr)                                                        \
    asm volatile("ldmatrix.sync.aligned.m8n8.x4.shared.b16 {%0,%1,%2,%3}, [%4];" \
        : "=r"((r)[0]), "=r"((r)[1]), "=r"((r)[2]), "=r"((r)[3]) : "r"(addr))

__device__ __forceinline__ void mma_tf32(float* c, const uint32_t* a,
                                         uint32_t b0, uint32_t b1) {
    asm volatile(
        "mma.sync.aligned.m16n8k8.row.col.f32.tf32.tf32.f32 "
        "{%0,%1,%2,%3}, {%4,%5,%6,%7}, {%8,%9}, {%0,%1,%2,%3};"
        : "+f"(c[0]), "+f"(c[1]), "+f"(c[2]), "+f"(c[3])
        : "r"(a[0]), "r"(a[1]), "r"(a[2]), "r"(a[3]), "r"(b0), "r"(b1));
}

__device__ __forceinline__ void mma_bf16(float* c, const uint32_t* a,
                                         uint32_t b0, uint32_t b1) {
    asm volatile(
        "mma.sync.aligned.m16n8k16.row.col.f32.bf16.bf16.f32 "
        "{%0,%1,%2,%3}, {%4,%5,%6,%7}, {%8,%9}, {%0,%1,%2,%3};"
        : "+f"(c[0]), "+f"(c[1]), "+f"(c[2]), "+f"(c[3])
        : "r"(a[0]), "r"(a[1]), "r"(a[2]), "r"(a[3]), "r"(b0), "r"(b1));
}

// =====================================================================
// Kernel A/B: grouped 5-tap conv as tf32 MMA.
// ONLY change vs R14: no per-fragment cvt.rna.tf32 on B operands
// (hardware reads the tf32 subset of raw fp32 bits — same convention
// already used for the A operand of kConvMMA since R4).
// =====================================================================
#define CAPAD 172
#define SPAD2 292
#define CWPAD 33
#define CIPAD 260

template<int MOC, bool ISQ>
__global__ __launch_bounds__(256, 2)
void kConv(const float* __restrict__ inp, const float* __restrict__ wgt,
           const float* __restrict__ bias, const float* __restrict__ mask)
{
    extern __shared__ float sf[];
    float* As    = sf;                      // MOC x CAPAD
    float* stage = sf + MOC * CAPAD;        // 32 x SPAD2

    const int tid  = threadIdx.x;
    const int lane = tid & 31, wid = tid >> 5;
    const int t0 = blockIdx.x * 256;
    const int w0 = blockIdx.x * 32;
    const int g  = blockIdx.y;
    const int b  = blockIdx.z;

    const float* Irow = inp + ((size_t)b * 128 + g * 32) * T_;
    const float* Arow = wgt + (size_t)g * MOC * 160;

    for (int idx = tid; idx < MOC * 40; idx += 256) {
        int row = idx / 40, c4 = idx - row * 40;
        float4 v = *(const float4*)(Arow + row * 160 + c4 * 4);
        v.x = to_tf32(v.x); v.y = to_tf32(v.y);
        v.z = to_tf32(v.z); v.w = to_tf32(v.w);
        *(float4*)&As[row * CAPAD + c4 * 4] = v;
    }

    {
        uint32_t sb = smem_u32(stage);
        #pragma unroll
        for (int it = 0; it < 9; it++) {
            int idx = tid + it * 256;
            int r = idx / 72, c4 = idx - r * 72;
            int t = t0 - 16 + c4 * 4;
            int tc = t < 0 ? 0 : (t > T_ - 4 ? T_ - 4 : t);
            int sz = (t >= 0 && t <= T_ - 4) ? 16 : 0;
            asm volatile("cp.async.cg.shared.global [%0], [%1], 16, %2;"
                         :: "r"(sb + (r * SPAD2 + c4 * 4) * 4),
                            "l"(Irow + (size_t)r * T_ + tc), "r"(sz));
        }
        asm volatile("cp.async.commit_group;");
        asm volatile("cp.async.wait_group 0;");
    }
    __syncthreads();

    constexpr int MF = MOC / 16;
    float acc[MF][4][4];
    #pragma unroll
    for (int mi = 0; mi < MF; mi++)
        #pragma unroll
        for (int nb = 0; nb < 4; nb++)
            #pragma unroll
            for (int e = 0; e < 4; e++) acc[mi][nb][e] = 0.f;

    const int n_warp = wid * 32;
    const int a_row  = (lane < 16) ? lane : (lane - 16);
    const int a_koff = (lane < 16) ? 0 : 4;
    const int b_k    = lane & 3;
    const int b_n    = lane >> 2;
    const uint32_t As0 = smem_u32(As);

    #pragma unroll 2
    for (int ch = 0; ch < 10; ch++) {
        #pragma unroll
        for (int ks = 0; ks < 2; ks++) {
            const int k0 = ks * 8;
            uint32_t ar[MF][4];
            #pragma unroll
            for (int mi = 0; mi < MF; mi++)
                LDSM4(ar[mi], As0 +
                    ((mi * 16 + a_row) * CAPAD + ch * 16 + k0 + a_koff) * 4);

            const int kga = ch * 16 + k0 + b_k;
            const int kgb = kga + 4;
            const int ica = kga / 5, kha = kga - ica * 5;
            const int icb = kgb / 5, khb = kgb - icb * 5;
            const float* rowA = stage + ica * SPAD2 + (kha - 2) * 8 + 16;
            const float* rowB = stage + icb * SPAD2 + (khb - 2) * 8 + 16;

            #pragma unroll
            for (int nb = 0; nb < 4; nb++) {
                const int n = n_warp + nb * 8 + b_n;
                uint32_t b0 = __float_as_uint(rowA[n]);
                uint32_t b1 = __float_as_uint(rowB[n]);
                #pragma unroll
                for (int mi = 0; mi < MF; mi++)
                    mma_tf32(acc[mi][nb], ar[mi], b0, b1);
            }
        }
    }
    __syncthreads();

    const int rg = lane >> 2;
    const int cg = (lane & 3) * 2;
    const float* bptr = bias + g * MOC;

    if (ISQ) {
        float* s2 = sf;
        #pragma unroll
        for (int mi = 0; mi < MF; mi++) {
            const int r0 = mi * 16 + rg, r1 = r0 + 8;
            const float bi0 = bptr[r0], bi1 = bptr[r1];
            #pragma unroll
            for (int nb = 0; nb < 4; nb++) {
                const int col = n_warp + nb * 8 + cg;
                const int w = col >> 3, p = col & 7;
                const float* c = acc[mi][nb];
                *(float2*)&s2[w * CIPAD + r0 * 8 + p] = make_float2(c[0] + bi0, c[1] + bi0);
                *(float2*)&s2[w * CIPAD + r1 * 8 + p] = make_float2(c[2] + bi1, c[3] + bi1);
            }
        }
        __syncthreads();
        const int w = tid >> 3, c64 = (tid & 7) * 32;
        float* dst = g_qr + ((size_t)b * W_ + w0 + w) * CP_ + g * 256 + c64;
        #pragma unroll
        for (int j = 0; j < 8; j++)
            *(float4*)(dst + j * 4) = *(const float4*)&s2[w * CIPAD + c64 + j * 4];
    } else {
        float* s2 = sf;
        const bool isK = (g < 2);
        const float* mrow = isK ?
            (mask + ((size_t)b * 128 + g * 64) * (size_t)T_ + t0) : nullptr;
        #pragma unroll
        for (int mi = 0; mi < MF; mi++) {
            const int r0 = mi * 16 + rg, r1 = r0 + 8;
            const float bi0 = bptr[r0], bi1 = bptr[r1];
            #pragma unroll
            for (int nb = 0; nb < 4; nb++) {
                const int col = n_warp + nb * 8 + cg;
                const int w = col >> 3, p = col & 7;
                const float* c = acc[mi][nb];
                float2 m0 = make_float2(0.f, 0.f), m1 = m0;
                if (isK) {
                    m0 = *(const float2*)(mrow + (size_t)r0 * T_ + col);
                    m1 = *(const float2*)(mrow + (size_t)r1 * T_ + col);
                }
                s2[(r0 * 8 + p)     * CWPAD + w] = c[0] + bi0 + m0.x;
                s2[(r0 * 8 + p + 1) * CWPAD + w] = c[1] + bi0 + m0.y;
                s2[(r1 * 8 + p)     * CWPAD + w] = c[2] + bi1 + m1.x;
                s2[(r1 * 8 + p + 1) * CWPAD + w] = c[3] + bi1 + m1.y;
            }
        }
        __syncthreads();
        #pragma unroll
        for (int h = 0; h < 2; h++) {
            const int i = tid + h * 256;
            const size_t rowi = (size_t)b * CP_ + (size_t)(g & 1) * 512 + i;
            if (isK) {
                float* drow = g_kt + rowi * W_ + w0;
                #pragma unroll
                for (int j = 0; j < 8; j++) {
                    float4 v;
                    v.x = s2[i * CWPAD + j * 4 + 0];
                    v.y = s2[i * CWPAD + j * 4 + 1];
                    v.z = s2[i * CWPAD + j * 4 + 2];
                    v.w = s2[i * CWPAD + j * 4 + 3];
                    *(float4*)(drow + j * 4) = v;
                }
            } else {
                uint16_t* drow = g_vth + rowi * W_ + w0;
                #pragma unroll
                for (int j = 0; j < 8; j++) {
                    uint2 pk;
                    pk.x = pack_bf16(s2[i * CWPAD + j * 4 + 0],
                                     s2[i * CWPAD + j * 4 + 1]);
                    pk.y = pack_bf16(s2[i * CWPAD + j * 4 + 2],
                                     s2[i * CWPAD + j * 4 + 3]);
                    *(uint2*)(drow + j * 4) = pk;
                }
            }
        }
    }
}

// =====================================================================
// Kernel C: row softmax of g_qr -> g_qh bf16 (unchanged)
// =====================================================================
__global__ __launch_bounds__(256, 4)
void kSoftQ()
{
    __shared__ float red[8];
    const int tid = threadIdx.x, lane = tid & 31, wrp = tid >> 5;
    const size_t off = ((size_t)blockIdx.y * W_ + blockIdx.x) * CP_;

    float4 v = *(const float4*)(g_qr + off + tid * 4);
    float mx = fmaxf(fmaxf(v.x, v.y), fmaxf(v.z, v.w));
    #pragma unroll
    for (int o = 16; o; o >>= 1)
        mx = fmaxf(mx, __shfl_xor_sync(0xffffffffu, mx, o));
    if (lane == 0) red[wrp] = mx;
    __syncthreads();
    float m = red[0];
    #pragma unroll
    for (int k = 1; k < 8; k++) m = fmaxf(m, red[k]);

    float4 e;
    e.x = __expf(v.x - m); e.y = __expf(v.y - m);
    e.z = __expf(v.z - m); e.w = __expf(v.w - m);
    float s = e.x + e.y + e.z + e.w;
    #pragma unroll
    for (int o = 16; o; o >>= 1)
        s += __shfl_xor_sync(0xffffffffu, s, o);
    __syncthreads();
    if (lane == 0) red[wrp] = s;
    __syncthreads();
    float tot = 0.f;
    #pragma unroll
    for (int k = 0; k < 8; k++) tot += red[k];
    float r = 1.f / tot;

    uint2 pk;
    pk.x = pack_bf16(e.x * r, e.y * r);
    pk.y = pack_bf16(e.z * r, e.w * r);
    *(uint2*)&g_qh[off + tid * 4] = pk;
}

// =====================================================================
// Kernel D: per-row (i) softmax over w of g_kt -> g_kth bf16 (unchanged)
// =====================================================================
__global__ __launch_bounds__(256, 4)
void kStatK()
{
    __shared__ float red[8];
    const int tid = threadIdx.x, lane = tid & 31, wrp = tid >> 5;
    const size_t off = ((size_t)blockIdx.y * CP_ + blockIdx.x) * (size_t)W_;

    float4 v0 = *(const float4*)(g_kt + off + tid * 4);
    float4 v1 = *(const float4*)(g_kt + off + 1024 + tid * 4);
    float mx = fmaxf(fmaxf(fmaxf(v0.x, v0.y), fmaxf(v0.z, v0.w)),
                     fmaxf(fmaxf(v1.x, v1.y), fmaxf(v1.z, v1.w)));
    #pragma unroll
    for (int o = 16; o; o >>= 1)
        mx = fmaxf(mx, __shfl_xor_sync(0xffffffffu, mx, o));
    if (lane == 0) red[wrp] = mx;
    __syncthreads();
    float m = red[0];
    #pragma unroll
    for (int k = 1; k < 8; k++) m = fmaxf(m, red[k]);

    float4 e0, e1;
    e0.x = __expf(v0.x - m); e0.y = __expf(v0.y - m);
    e0.z = __expf(v0.z - m); e0.w = __expf(v0.w - m);
    e1.x = __expf(v1.x - m); e1.y = __expf(v1.y - m);
    e1.z = __expf(v1.z - m); e1.w = __expf(v1.w - m);
    float s = e0.x + e0.y + e0.z + e0.w + e1.x + e1.y + e1.z + e1.w;
    #pragma unroll
    for (int o = 16; o; o >>= 1)
        s += __shfl_xor_sync(0xffffffffu, s, o);
    __syncthreads();
    if (lane == 0) red[wrp] = s;
    __syncthreads();
    float tot = 0.f;
    #pragma unroll
    for (int k = 0; k < 8; k++) tot += red[k];
    float r = 1.f / tot;

    uint2 p0, p1;
    p0.x = pack_bf16(e0.x * r, e0.y * r);
    p0.y = pack_bf16(e0.z * r, e0.w * r);
    p1.x = pack_bf16(e1.x * r, e1.y * r);
    p1.y = pack_bf16(e1.z * r, e1.w * r);
    *(uint2*)&g_kth[off + tid * 4]        = p0;
    *(uint2*)&g_kth[off + 1024 + tid * 4] = p1;
}

// =====================================================================
// Kernel E/F: bf16 mma.sync m16n8k16 GEMM, 128x128 tile, 256 threads,
// BK=64, 3 stages, wait_group 1 (exact R13/R14 version).
// =====================================================================
#define BK2     64
#define BKPAD2  72                 // elements (144 B row stride)
#define STG2    (256 * BKPAD2)     // bf16 elements per stage
#define GSTAGES 3

template<int KTOT, int MTOT, int EPI>
__global__ __launch_bounds__(256, 2)
void kGemmMMA()
{
    extern __shared__ __align__(16) char smemc[];
    uint16_t* smemh = (uint16_t*)smemc;
    const int tid  = threadIdx.x;
    const int lane = tid & 31, wid = tid >> 5;
    const int b  = blockIdx.z;
    const int n0 = blockIdx.x * 128;
    const int m0 = blockIdx.y * 128;

    const uint16_t* A  = (EPI == 0) ? g_vth : g_qh;
    const uint16_t* Bp = (EPI == 0) ? g_kth : g_kvh;

    const uint16_t* Ag = A  + (size_t)b * MTOT * KTOT + (size_t)m0 * KTOT;
    const uint16_t* Bg = Bp + (size_t)b * 1024 * KTOT + (size_t)n0 * KTOT;

    const uint32_t smem0 = smem_u32(smemh);
    const int NT = KTOT / BK2;

    auto load_stage = [&](int s, int koff) {
        uint32_t sb = smem0 + (s % GSTAGES) * STG2 * 2;
        #pragma unroll
        for (int it = 0; it < 8; it++) {
            int idx = tid + it * 256;            // 0..2047 (16B units)
            int r = idx >> 3, c = (idx & 7) * 8;
            const uint16_t* src = (r < 128)
                ? Ag + (size_t)r * KTOT + koff + c
                : Bg + (size_t)(r - 128) * KTOT + koff + c;
            asm volatile("cp.async.cg.shared.global [%0], [%1], 16;"
                         :: "r"(sb + (r * BKPAD2 + c) * 2), "l"(src));
        }
        asm volatile("cp.async.commit_group;");
    };

    #pragma unroll
    for (int s = 0; s < 2; s++) load_stage(s, s * BK2);

    const int m_warp = (wid & 1) * 64;
    const int n_warp = (wid >> 1) * 32;

    float acc[4][4][4];
    #pragma unroll
    for (int mi = 0; mi < 4; mi++)
        #pragma unroll
        for (int nb = 0; nb < 4; nb++)
            #pragma unroll
            for (int e = 0; e < 4; e++) acc[mi][nb][e] = 0.f;

    const int frow = lane & 15;            // m/n row within 16
    const int fkoff = (lane >> 4) * 8;     // k element offset

    for (int t = 0; t < NT; t++) {
        asm volatile("cp.async.wait_group 1;");
        __syncthreads();

        if (t + 2 < NT) load_stage(t + 2, (t + 2) * BK2);
        else            asm volatile("cp.async.commit_group;");

        const uint32_t As = smem0 + (t % GSTAGES) * STG2 * 2;
        const uint32_t Bs = As + 128 * BKPAD2 * 2;

        #pragma unroll
        for (int ks = 0; ks < 4; ks++) {
            const int k0 = ks * 16;
            uint32_t ar[4][4];
            #pragma unroll
            for (int mi = 0; mi < 4; mi++)
                LDSM4(ar[mi], As +
                    ((m_warp + mi * 16 + frow) * BKPAD2 + k0 + fkoff) * 2);
            uint32_t br[2][4];
            #pragma unroll
            for (int nb2 = 0; nb2 < 2; nb2++)
                LDSM4(br[nb2], Bs +
                    ((n_warp + nb2 * 16 + frow) * BKPAD2 + k0 + fkoff) * 2);
            #pragma unroll
            for (int mi = 0; mi < 4; mi++)
                #pragma unroll
                for (int nb = 0; nb < 4; nb++)
                    mma_bf16(acc[mi][nb], ar[mi],
                             br[nb >> 1][nb & 1],
                             br[nb >> 1][(nb & 1) + 2]);
        }
    }

    const int rg = lane >> 2;
    const int cg = (lane & 3) * 2;
    #pragma unroll
    for (int mi = 0; mi < 4; mi++) {
        const int row = m0 + m_warp + mi * 16 + rg;
        #pragma unroll
        for (int nb = 0; nb < 4; nb++) {
            const int col = n0 + n_warp + nb * 8 + cg;
            const float* c = acc[mi][nb];
            if (EPI == 0) {
                *(uint32_t*)&g_kvh[((size_t)b * CP_ + row)     * CP_ + col] =
                    pack_bf16(c[0], c[1]);
                *(uint32_t*)&g_kvh[((size_t)b * CP_ + row + 8) * CP_ + col] =
                    pack_bf16(c[2], c[3]);
            } else {
                const int oc = col >> 3, p = col & 7;
                float* base = &g_at[((size_t)b * MIDC_ + oc) * T_];
                *(float2*)&base[(size_t)row * 8 + p]       = make_float2(c[0], c[1]);
                *(float2*)&base[(size_t)(row + 8) * 8 + p] = make_float2(c[2], c[3]);
            }
        }
    }
}

// =====================================================================
// Kernel G: conv1d via tf32 mma.sync, staging-tile B path, K-chunk 32
// (R14 version). ONLY change: no per-fragment cvt.rna.tf32 on B.
// =====================================================================
#define CBK    32
#define CBKPAD 36
#define SROWS  12
#define SPAD   140
__global__ __launch_bounds__(256, 2)
void kConvMMA(const float* __restrict__ wOut, const float* __restrict__ bOut,
              float* __restrict__ out)
{
    __shared__ __align__(16) float As[2][128 * CBKPAD];
    __shared__ __align__(16) float Bstg[2][SROWS * SPAD];

    const int tid  = threadIdx.x;
    const int lane = tid & 31, wid = tid >> 5;
    const int b  = blockIdx.y;
    const int t0 = blockIdx.x * 128;

    const float* Ab = &g_at[(size_t)b * MIDC_ * T_];

    auto load_chunk = [&](int ch) {
        const int buf = ch & 1;
        uint32_t ab = smem_u32(&As[buf][0]);
        #pragma unroll
        for (int it = 0; it < 4; it++) {
            int idx = tid + it * 256;
            int r = idx >> 3, c = (idx & 7) * 4;
            asm volatile("cp.async.cg.shared.global [%0], [%1], 16;"
                         :: "r"(ab + (r * CBKPAD + c) * 4),
                            "l"(wOut + (size_t)r * 384 + ch * CBK + c));
        }
        const int m_base = (ch * CBK) / 3;
        uint32_t bb = smem_u32(&Bstg[buf][0]);
        #pragma unroll
        for (int it = 0; it < 2; it++) {
            int idx = tid + it * 256;
            if (idx < SROWS * 34) {
                int r = idx / 34, c4 = idx - r * 34;
                int mr = m_base + r;
                int t = t0 - 4 + c4 * 4;
                int tc = t < 0 ? 0 : (t > T_ - 4 ? T_ - 4 : t);
                int sz = (mr < 128 && t >= 0 && t <= T_ - 4) ? 16 : 0;
                int mrc = mr < 128 ? mr : 127;
                const float* src = Ab + (size_t)mrc * T_ + tc;
                asm volatile("cp.async.cg.shared.global [%0], [%1], 16, %2;"
                             :: "r"(bb + (r * SPAD + c4 * 4) * 4), "l"(src), "r"(sz));
            }
        }
        asm volatile("cp.async.commit_group;");
    };

    const int m_warp = (wid & 1) * 64;
    const int n_warp = (wid >> 1) * 32;

    float acc[4][4][4];
    #pragma unroll
    for (int mi = 0; mi < 4; mi++)
        #pragma unroll
        for (int nb = 0; nb < 4; nb++)
            #pragma unroll
            for (int e = 0; e < 4; e++) acc[mi][nb][e] = 0.f;

    const int a_row  = (lane < 16) ? lane : (lane - 16);
    const int a_koff = (lane < 16) ? 0 : 4;
    const int b_k    = lane & 3;
    const int b_n    = lane >> 2;

    const uint32_t As0 = smem_u32(&As[0][0]);

    load_chunk(0);

    for (int ch = 0; ch < 12; ch++) {
        if (ch < 11) {
            load_chunk(ch + 1);
            asm volatile("cp.async.wait_group 1;");
        } else {
            asm volatile("cp.async.wait_group 0;");
        }
        __syncthreads();

        const int buf = ch & 1;
        const int m_base = (ch * CBK) / 3;
        const uint32_t Asb = As0 + buf * (128 * CBKPAD * 4);
        const float*   stg = &Bstg[buf][0];

        #pragma unroll
        for (int ks = 0; ks < 4; ks++) {
            const int k0 = ks * 8;
            uint32_t ar[4][4];
            #pragma unroll
            for (int mi = 0; mi < 4; mi++) {
                uint32_t addr = Asb +
                    ((m_warp + mi * 16 + a_row) * CBKPAD + k0 + a_koff) * 4;
                LDSM4(ar[mi], addr);
            }
            const int kg0 = ch * CBK + k0 + b_k;
            const int kg1 = kg0 + 4;
            const int mr0 = kg0 / 3, kt0 = kg0 - mr0 * 3;
            const int mr1 = kg1 / 3, kt1 = kg1 - mr1 * 3;
            const float* row0 = stg + (mr0 - m_base) * SPAD + 3 + kt0;
            const float* row1 = stg + (mr1 - m_base) * SPAD + 3 + kt1;
            #pragma unroll
            for (int nb = 0; nb < 4; nb++) {
                const int n = n_warp + nb * 8 + b_n;
                uint32_t b0 = __float_as_uint(row0[n]);
                uint32_t b1 = __float_as_uint(row1[n]);
                #pragma unroll
                for (int mi = 0; mi < 4; mi++)
                    mma_tf32(acc[mi][nb], ar[mi], b0, b1);
            }
        }
        __syncthreads();
    }

    const int rg = lane >> 2;
    const int cg = (lane & 3) * 2;
    #pragma unroll
    for (int mi = 0; mi < 4; mi++) {
        const int row = m_warp + mi * 16 + rg;
        const float bi0 = __ldg(&bOut[row]);
        const float bi1 = __ldg(&bOut[row + 8]);
        float* r0 = out + ((size_t)b * 128 + row)     * T_ + t0;
        float* r1 = out + ((size_t)b * 128 + row + 8) * T_ + t0;
        #pragma unroll
        for (int nb = 0; nb < 4; nb++) {
            const int col = n_warp + nb * 8 + cg;
            const float* c = acc[mi][nb];
            *(float2*)(r0 + col) = make_float2(c[0] + bi0, c[1] + bi0);
            *(float2*)(r1 + col) = make_float2(c[2] + bi1, c[3] + bi1);
        }
    }
}

// =====================================================================
// launcher
// =====================================================================
extern "C" void kernel_launch(void* const* d_in, const int* in_sizes, int n_in,
                              void* d_out, int out_size)
{
    (void)in_sizes; (void)n_in; (void)out_size;
    const float* x    = (const float*)d_in[0];
    const float* cond = (const float*)d_in[1];
    const float* mask = (const float*)d_in[2];
    const float* wQ   = (const float*)d_in[3];
    const float* bQ   = (const float*)d_in[4];
    const float* wKV  = (const float*)d_in[5];
    const float* bKV  = (const float*)d_in[6];
    const float* wOut = (const float*)d_in[7];
    const float* bOut = (const float*)d_in[8];
    float* out = (float*)d_out;

    const size_t smQ  = (size_t)(32 * CAPAD + 32 * SPAD2) * sizeof(float);   // ~59 KB
    const size_t smKV = (size_t)(64 * CAPAD + 32 * SPAD2) * sizeof(float);   // ~81 KB
    const size_t smG  = (size_t)GSTAGES * STG2 * sizeof(uint16_t);           // 110592 B
    cudaFuncSetAttribute(kConv<32, true>,
                         cudaFuncAttributeMaxDynamicSharedMemorySize, (int)smQ);
    cudaFuncSetAttribute(kConv<64, false>,
                         cudaFuncAttributeMaxDynamicSharedMemorySize, (int)smKV);
    cudaFuncSetAttribute(kGemmMMA<2048, 1024, 0>,
                         cudaFuncAttributeMaxDynamicSharedMemorySize, (int)smG);
    cudaFuncSetAttribute(kGemmMMA<1024, 2048, 1>,
                         cudaFuncAttributeMaxDynamicSharedMemorySize, (int)smG);

    kConv<32, true ><<<dim3(T_ / 256, 4, B_), 256, smQ >>>(cond, wQ,  bQ,  nullptr);
    kConv<64, false><<<dim3(T_ / 256, 4, B_), 256, smKV>>>(x,    wKV, bKV, mask);
    kSoftQ<<<dim3(W_, B_), 256>>>();
    kStatK<<<dim3(CP_, B_), 256>>>();
    // GEMM1: D1[i][j] = sum_w vth[i][w] * kth[j][w]  (M=1024, N=1024, K=2048)
    kGemmMMA<2048, 1024, 0><<<dim3(CP_ / 128, CP_ / 128, B_), 256, smG>>>();
    // GEMM2: D2[w][i] = sum_j qh[w][j] * kvh[i][j]   (M=2048, N=1024, K=1024)
    kGemmMMA<1024, 2048, 1><<<dim3(CP_ / 128, W_ / 128, B_), 256, smG>>>();
    kConvMMA<<<dim3(T_ / 128, B_), 256>>>(wOut, bOut, out);
}

// round 16
// speedup vs baseline: 1.0025x; 1.0025x over previous
#include <cuda_runtime.h>
#include <cstdint>

// ---------------- problem constants ----------------
#define B_    16
#define C_    128
#define T_    16384
#define W_    2048      // wordnum = T/patch
#define P_    8
#define MIDC_ 128
#define CP_   1024      // MIDC * P

// ---------------- scratch (device globals; allocation-free rule) ----------------
__device__ float    g_qr [(size_t)B_ * W_ * CP_];   // raw Q (pre-softmax) [b][w][i]
__device__ float    g_kt [(size_t)B_ * CP_ * W_];   // raw K^T (pre-softmax) [b][i][w]
__device__ uint16_t g_qh [(size_t)B_ * W_ * CP_];   // bf16 softmaxed Q    [b][w][i]
__device__ uint16_t g_kth[(size_t)B_ * CP_ * W_];   // bf16 softmax(K)^T   [b][i][w]
__device__ uint16_t g_vth[(size_t)B_ * CP_ * W_];   // bf16 V^T            [b][i][w]
__device__ uint16_t g_kvh[(size_t)B_ * CP_ * CP_];  // bf16 kv_mat^T       [b][i][j]
__device__ float    g_at [(size_t)B_ * MIDC_ * T_]; // attn out fp32       [b][m][t]

// ---------------- helpers ----------------
__device__ __forceinline__ uint32_t smem_u32(const void* p) {
    uint32_t a;
    asm("{ .reg .u64 t; cvta.to.shared.u64 t, %1; cvt.u32.u64 %0, t; }"
        : "=r"(a) : "l"(p));
    return a;
}

__device__ __forceinline__ float to_tf32(float x) {
    uint32_t u;
    asm("cvt.rna.tf32.f32 %0, %1;" : "=r"(u) : "f"(x));
    return __uint_as_float(u);
}

// pack two floats -> bf16x2 (lo = first arg)
__device__ __forceinline__ uint32_t pack_bf16(float lo, float hi) {
    uint32_t r;
    asm("cvt.rn.bf16x2.f32 %0, %1, %2;" : "=r"(r) : "f"(hi), "f"(lo));
    return r;
}

#define LDSM4(r, addr)                                                        \
    asm volatile("ldmatrix.sync.aligned.m8n8.x4.shared.b16 {%0,%1,%2,%3}, [%4];" \
        : "=r"((r)[0]), "=r"((r)[1]), "=r"((r)[2]), "=r"((r)[3]) : "r"(addr))

__device__ __forceinline__ void mma_tf32(float* c, const uint32_t* a,
                                         uint32_t b0, uint32_t b1) {
    asm volatile(
        "mma.sync.aligned.m16n8k8.row.col.f32.tf32.tf32.f32 "
        "{%0,%1,%2,%3}, {%4,%5,%6,%7}, {%8,%9}, {%0,%1,%2,%3};"
        : "+f"(c[0]), "+f"(c[1]), "+f"(c[2]), "+f"(c[3])
        : "r"(a[0]), "r"(a[1]), "r"(a[2]), "r"(a[3]), "r"(b0), "r"(b1));
}

__device__ __forceinline__ void mma_bf16(float* c, const uint32_t* a,
                                         uint32_t b0, uint32_t b1) {
    asm volatile(
        "mma.sync.aligned.m16n8k16.row.col.f32.bf16.bf16.f32 "
        "{%0,%1,%2,%3}, {%4,%5,%6,%7}, {%8,%9}, {%0,%1,%2,%3};"
        : "+f"(c[0]), "+f"(c[1]), "+f"(c[2]), "+f"(c[3])
        : "r"(a[0]), "r"(a[1]), "r"(a[2]), "r"(a[3]), "r"(b0), "r"(b1));
}

// =====================================================================
// Kernel A/B: grouped 5-tap conv as tf32 MMA (R14 exact: cvt.rna on B
// restored — measured free in time, preserves precision margin).
// =====================================================================
#define CAPAD 172
#define SPAD2 292
#define CWPAD 33
#define CIPAD 260

template<int MOC, bool ISQ>
__global__ __launch_bounds__(256, 2)
void kConv(const float* __restrict__ inp, const float* __restrict__ wgt,
           const float* __restrict__ bias, const float* __restrict__ mask)
{
    extern __shared__ float sf[];
    float* As    = sf;                      // MOC x CAPAD
    float* stage = sf + MOC * CAPAD;        // 32 x SPAD2

    const int tid  = threadIdx.x;
    const int lane = tid & 31, wid = tid >> 5;
    const int t0 = blockIdx.x * 256;
    const int w0 = blockIdx.x * 32;
    const int g  = blockIdx.y;
    const int b  = blockIdx.z;

    const float* Irow = inp + ((size_t)b * 128 + g * 32) * T_;
    const float* Arow = wgt + (size_t)g * MOC * 160;

    for (int idx = tid; idx < MOC * 40; idx += 256) {
        int row = idx / 40, c4 = idx - row * 40;
        float4 v = *(const float4*)(Arow + row * 160 + c4 * 4);
        v.x = to_tf32(v.x); v.y = to_tf32(v.y);
        v.z = to_tf32(v.z); v.w = to_tf32(v.w);
        *(float4*)&As[row * CAPAD + c4 * 4] = v;
    }

    {
        uint32_t sb = smem_u32(stage);
        #pragma unroll
        for (int it = 0; it < 9; it++) {
            int idx = tid + it * 256;
            int r = idx / 72, c4 = idx - r * 72;
            int t = t0 - 16 + c4 * 4;
            int tc = t < 0 ? 0 : (t > T_ - 4 ? T_ - 4 : t);
            int sz = (t >= 0 && t <= T_ - 4) ? 16 : 0;
            asm volatile("cp.async.cg.shared.global [%0], [%1], 16, %2;"
                         :: "r"(sb + (r * SPAD2 + c4 * 4) * 4),
                            "l"(Irow + (size_t)r * T_ + tc), "r"(sz));
        }
        asm volatile("cp.async.commit_group;");
        asm volatile("cp.async.wait_group 0;");
    }
    __syncthreads();

    constexpr int MF = MOC / 16;
    float acc[MF][4][4];
    #pragma unroll
    for (int mi = 0; mi < MF; mi++)
        #pragma unroll
        for (int nb = 0; nb < 4; nb++)
            #pragma unroll
            for (int e = 0; e < 4; e++) acc[mi][nb][e] = 0.f;

    const int n_warp = wid * 32;
    const int a_row  = (lane < 16) ? lane : (lane - 16);
    const int a_koff = (lane < 16) ? 0 : 4;
    const int b_k    = lane & 3;
    const int b_n    = lane >> 2;
    const uint32_t As0 = smem_u32(As);

    #pragma unroll 2
    for (int ch = 0; ch < 10; ch++) {
        #pragma unroll
        for (int ks = 0; ks < 2; ks++) {
            const int k0 = ks * 8;
            uint32_t ar[MF][4];
            #pragma unroll
            for (int mi = 0; mi < MF; mi++)
                LDSM4(ar[mi], As0 +
                    ((mi * 16 + a_row) * CAPAD + ch * 16 + k0 + a_koff) * 4);

            const int kga = ch * 16 + k0 + b_k;
            const int kgb = kga + 4;
            const int ica = kga / 5, kha = kga - ica * 5;
            const int icb = kgb / 5, khb = kgb - icb * 5;
            const float* rowA = stage + ica * SPAD2 + (kha - 2) * 8 + 16;
            const float* rowB = stage + icb * SPAD2 + (khb - 2) * 8 + 16;

            #pragma unroll
            for (int nb = 0; nb < 4; nb++) {
                const int n = n_warp + nb * 8 + b_n;
                uint32_t b0 = __float_as_uint(to_tf32(rowA[n]));
                uint32_t b1 = __float_as_uint(to_tf32(rowB[n]));
                #pragma unroll
                for (int mi = 0; mi < MF; mi++)
                    mma_tf32(acc[mi][nb], ar[mi], b0, b1);
            }
        }
    }
    __syncthreads();

    const int rg = lane >> 2;
    const int cg = (lane & 3) * 2;
    const float* bptr = bias + g * MOC;

    if (ISQ) {
        float* s2 = sf;
        #pragma unroll
        for (int mi = 0; mi < MF; mi++) {
            const int r0 = mi * 16 + rg, r1 = r0 + 8;
            const float bi0 = bptr[r0], bi1 = bptr[r1];
            #pragma unroll
            for (int nb = 0; nb < 4; nb++) {
                const int col = n_warp + nb * 8 + cg;
                const int w = col >> 3, p = col & 7;
                const float* c = acc[mi][nb];
                *(float2*)&s2[w * CIPAD + r0 * 8 + p] = make_float2(c[0] + bi0, c[1] + bi0);
                *(float2*)&s2[w * CIPAD + r1 * 8 + p] = make_float2(c[2] + bi1, c[3] + bi1);
            }
        }
        __syncthreads();
        const int w = tid >> 3, c64 = (tid & 7) * 32;
        float* dst = g_qr + ((size_t)b * W_ + w0 + w) * CP_ + g * 256 + c64;
        #pragma unroll
        for (int j = 0; j < 8; j++)
            *(float4*)(dst + j * 4) = *(const float4*)&s2[w * CIPAD + c64 + j * 4];
    } else {
        float* s2 = sf;
        const bool isK = (g < 2);
        const float* mrow = isK ?
            (mask + ((size_t)b * 128 + g * 64) * (size_t)T_ + t0) : nullptr;
        #pragma unroll
        for (int mi = 0; mi < MF; mi++) {
            const int r0 = mi * 16 + rg, r1 = r0 + 8;
            const float bi0 = bptr[r0], bi1 = bptr[r1];
            #pragma unroll
            for (int nb = 0; nb < 4; nb++) {
                const int col = n_warp + nb * 8 + cg;
                const int w = col >> 3, p = col & 7;
                const float* c = acc[mi][nb];
                float2 m0 = make_float2(0.f, 0.f), m1 = m0;
                if (isK) {
                    m0 = *(const float2*)(mrow + (size_t)r0 * T_ + col);
                    m1 = *(const float2*)(mrow + (size_t)r1 * T_ + col);
                }
                s2[(r0 * 8 + p)     * CWPAD + w] = c[0] + bi0 + m0.x;
                s2[(r0 * 8 + p + 1) * CWPAD + w] = c[1] + bi0 + m0.y;
                s2[(r1 * 8 + p)     * CWPAD + w] = c[2] + bi1 + m1.x;
                s2[(r1 * 8 + p + 1) * CWPAD + w] = c[3] + bi1 + m1.y;
            }
        }
        __syncthreads();
        #pragma unroll
        for (int h = 0; h < 2; h++) {
            const int i = tid + h * 256;
            const size_t rowi = (size_t)b * CP_ + (size_t)(g & 1) * 512 + i;
            if (isK) {
                float* drow = g_kt + rowi * W_ + w0;
                #pragma unroll
                for (int j = 0; j < 8; j++) {
                    float4 v;
                    v.x = s2[i * CWPAD + j * 4 + 0];
                    v.y = s2[i * CWPAD + j * 4 + 1];
                    v.z = s2[i * CWPAD + j * 4 + 2];
                    v.w = s2[i * CWPAD + j * 4 + 3];
                    *(float4*)(drow + j * 4) = v;
                }
            } else {
                uint16_t* drow = g_vth + rowi * W_ + w0;
                #pragma unroll
                for (int j = 0; j < 8; j++) {
                    uint2 pk;
                    pk.x = pack_bf16(s2[i * CWPAD + j * 4 + 0],
                                     s2[i * CWPAD + j * 4 + 1]);
                    pk.y = pack_bf16(s2[i * CWPAD + j * 4 + 2],
                                     s2[i * CWPAD + j * 4 + 3]);
                    *(uint2*)(drow + j * 4) = pk;
                }
            }
        }
    }
}

// =====================================================================
// Kernel C: fused softmax kernel.
//   blocks [0, W)        : row softmax of g_qr (1024) -> g_qh bf16
//   blocks [W, W+CP)     : row softmax of g_kt (2048) -> g_kth bf16
// One launch instead of two; both phases are DRAM-bound and share waves.
// =====================================================================
__global__ __launch_bounds__(256, 4)
void kSoftAll()
{
    __shared__ float red[8];
    const int tid = threadIdx.x, lane = tid & 31, wrp = tid >> 5;
    const int bx = blockIdx.x, b = blockIdx.y;

    if (bx < W_) {
        // ---- Q path: 1024 elements ----
        const size_t off = ((size_t)b * W_ + bx) * CP_;
        float4 v = *(const float4*)(g_qr + off + tid * 4);
        float mx = fmaxf(fmaxf(v.x, v.y), fmaxf(v.z, v.w));
        #pragma unroll
        for (int o = 16; o; o >>= 1)
            mx = fmaxf(mx, __shfl_xor_sync(0xffffffffu, mx, o));
        if (lane == 0) red[wrp] = mx;
        __syncthreads();
        float m = red[0];
        #pragma unroll
        for (int k = 1; k < 8; k++) m = fmaxf(m, red[k]);

        float4 e;
        e.x = __expf(v.x - m); e.y = __expf(v.y - m);
        e.z = __expf(v.z - m); e.w = __expf(v.w - m);
        float s = e.x + e.y + e.z + e.w;
        #pragma unroll
        for (int o = 16; o; o >>= 1)
            s += __shfl_xor_sync(0xffffffffu, s, o);
        __syncthreads();
        if (lane == 0) red[wrp] = s;
        __syncthreads();
        float tot = 0.f;
        #pragma unroll
        for (int k = 0; k < 8; k++) tot += red[k];
        float r = 1.f / tot;

        uint2 pk;
        pk.x = pack_bf16(e.x * r, e.y * r);
        pk.y = pack_bf16(e.z * r, e.w * r);
        *(uint2*)&g_qh[off + tid * 4] = pk;
    } else {
        // ---- K path: 2048 elements ----
        const int i = bx - W_;
        const size_t off = ((size_t)b * CP_ + i) * (size_t)W_;
        float4 v0 = *(const float4*)(g_kt + off + tid * 4);
        float4 v1 = *(const float4*)(g_kt + off + 1024 + tid * 4);
        float mx = fmaxf(fmaxf(fmaxf(v0.x, v0.y), fmaxf(v0.z, v0.w)),
                         fmaxf(fmaxf(v1.x, v1.y), fmaxf(v1.z, v1.w)));
        #pragma unroll
        for (int o = 16; o; o >>= 1)
            mx = fmaxf(mx, __shfl_xor_sync(0xffffffffu, mx, o));
        if (lane == 0) red[wrp] = mx;
        __syncthreads();
        float m = red[0];
        #pragma unroll
        for (int k = 1; k < 8; k++) m = fmaxf(m, red[k]);

        float4 e0, e1;
        e0.x = __expf(v0.x - m); e0.y = __expf(v0.y - m);
        e0.z = __expf(v0.z - m); e0.w = __expf(v0.w - m);
        e1.x = __expf(v1.x - m); e1.y = __expf(v1.y - m);
        e1.z = __expf(v1.z - m); e1.w = __expf(v1.w - m);
        float s = e0.x + e0.y + e0.z + e0.w + e1.x + e1.y + e1.z + e1.w;
        #pragma unroll
        for (int o = 16; o; o >>= 1)
            s += __shfl_xor_sync(0xffffffffu, s, o);
        __syncthreads();
        if (lane == 0) red[wrp] = s;
        __syncthreads();
        float tot = 0.f;
        #pragma unroll
        for (int k = 0; k < 8; k++) tot += red[k];
        float r = 1.f / tot;

        uint2 p0, p1;
        p0.x = pack_bf16(e0.x * r, e0.y * r);
        p0.y = pack_bf16(e0.z * r, e0.w * r);
        p1.x = pack_bf16(e1.x * r, e1.y * r);
        p1.y = pack_bf16(e1.z * r, e1.w * r);
        *(uint2*)&g_kth[off + tid * 4]        = p0;
        *(uint2*)&g_kth[off + 1024 + tid * 4] = p1;
    }
}

// =====================================================================
// Kernel E/F: bf16 mma.sync m16n8k16 GEMM, 128x128 tile, 256 threads,
// BK=64, 3 stages, wait_group 1 (exact R13/R14 version).
// =====================================================================
#define BK2     64
#define BKPAD2  72                 // elements (144 B row stride)
#define STG2    (256 * BKPAD2)     // bf16 elements per stage
#define GSTAGES 3

template<int KTOT, int MTOT, int EPI>
__global__ __launch_bounds__(256, 2)
void kGemmMMA()
{
    extern __shared__ __align__(16) char smemc[];
    uint16_t* smemh = (uint16_t*)smemc;
    const int tid  = threadIdx.x;
    const int lane = tid & 31, wid = tid >> 5;
    const int b  = blockIdx.z;
    const int n0 = blockIdx.x * 128;
    const int m0 = blockIdx.y * 128;

    const uint16_t* A  = (EPI == 0) ? g_vth : g_qh;
    const uint16_t* Bp = (EPI == 0) ? g_kth : g_kvh;

    const uint16_t* Ag = A  + (size_t)b * MTOT * KTOT + (size_t)m0 * KTOT;
    const uint16_t* Bg = Bp + (size_t)b * 1024 * KTOT + (size_t)n0 * KTOT;

    const uint32_t smem0 = smem_u32(smemh);
    const int NT = KTOT / BK2;

    auto load_stage = [&](int s, int koff) {
        uint32_t sb = smem0 + (s % GSTAGES) * STG2 * 2;
        #pragma unroll
        for (int it = 0; it < 8; it++) {
            int idx = tid + it * 256;            // 0..2047 (16B units)
            int r = idx >> 3, c = (idx & 7) * 8;
            const uint16_t* src = (r < 128)
                ? Ag + (size_t)r * KTOT + koff + c
                : Bg + (size_t)(r - 128) * KTOT + koff + c;
            asm volatile("cp.async.cg.shared.global [%0], [%1], 16;"
                         :: "r"(sb + (r * BKPAD2 + c) * 2), "l"(src));
        }
        asm volatile("cp.async.commit_group;");
    };

    #pragma unroll
    for (int s = 0; s < 2; s++) load_stage(s, s * BK2);

    const int m_warp = (wid & 1) * 64;
    const int n_warp = (wid >> 1) * 32;

    float acc[4][4][4];
    #pragma unroll
    for (int mi = 0; mi < 4; mi++)
        #pragma unroll
        for (int nb = 0; nb < 4; nb++)
            #pragma unroll
            for (int e = 0; e < 4; e++) acc[mi][nb][e] = 0.f;

    const int frow = lane & 15;            // m/n row within 16
    const int fkoff = (lane >> 4) * 8;     // k element offset

    for (int t = 0; t < NT; t++) {
        asm volatile("cp.async.wait_group 1;");
        __syncthreads();

        if (t + 2 < NT) load_stage(t + 2, (t + 2) * BK2);
        else            asm volatile("cp.async.commit_group;");

        const uint32_t As = smem0 + (t % GSTAGES) * STG2 * 2;
        const uint32_t Bs = As + 128 * BKPAD2 * 2;

        #pragma unroll
        for (int ks = 0; ks < 4; ks++) {
            const int k0 = ks * 16;
            uint32_t ar[4][4];
            #pragma unroll
            for (int mi = 0; mi < 4; mi++)
                LDSM4(ar[mi], As +
                    ((m_warp + mi * 16 + frow) * BKPAD2 + k0 + fkoff) * 2);
            uint32_t br[2][4];
            #pragma unroll
            for (int nb2 = 0; nb2 < 2; nb2++)
                LDSM4(br[nb2], Bs +
                    ((n_warp + nb2 * 16 + frow) * BKPAD2 + k0 + fkoff) * 2);
            #pragma unroll
            for (int mi = 0; mi < 4; mi++)
                #pragma unroll
                for (int nb = 0; nb < 4; nb++)
                    mma_bf16(acc[mi][nb], ar[mi],
                             br[nb >> 1][nb & 1],
                             br[nb >> 1][(nb & 1) + 2]);
        }
    }

    const int rg = lane >> 2;
    const int cg = (lane & 3) * 2;
    #pragma unroll
    for (int mi = 0; mi < 4; mi++) {
        const int row = m0 + m_warp + mi * 16 + rg;
        #pragma unroll
        for (int nb = 0; nb < 4; nb++) {
            const int col = n0 + n_warp + nb * 8 + cg;
            const float* c = acc[mi][nb];
            if (EPI == 0) {
                *(uint32_t*)&g_kvh[((size_t)b * CP_ + row)     * CP_ + col] =
                    pack_bf16(c[0], c[1]);
                *(uint32_t*)&g_kvh[((size_t)b * CP_ + row + 8) * CP_ + col] =
                    pack_bf16(c[2], c[3]);
            } else {
                const int oc = col >> 3, p = col & 7;
                float* base = &g_at[((size_t)b * MIDC_ + oc) * T_];
                *(float2*)&base[(size_t)row * 8 + p]       = make_float2(c[0], c[1]);
                *(float2*)&base[(size_t)(row + 8) * 8 + p] = make_float2(c[2], c[3]);
            }
        }
    }
}

// =====================================================================
// Kernel G: conv1d via tf32 mma.sync, staging-tile B path, K-chunk 32
// (R14 exact: cvt.rna on B restored).
// =====================================================================
#define CBK    32
#define CBKPAD 36
#define SROWS  12
#define SPAD   140
__global__ __launch_bounds__(256, 2)
void kConvMMA(const float* __restrict__ wOut, const float* __restrict__ bOut,
              float* __restrict__ out)
{
    __shared__ __align__(16) float As[2][128 * CBKPAD];
    __shared__ __align__(16) float Bstg[2][SROWS * SPAD];

    const int tid  = threadIdx.x;
    const int lane = tid & 31, wid = tid >> 5;
    const int b  = blockIdx.y;
    const int t0 = blockIdx.x * 128;

    const float* Ab = &g_at[(size_t)b * MIDC_ * T_];

    auto load_chunk = [&](int ch) {
        const int buf = ch & 1;
        uint32_t ab = smem_u32(&As[buf][0]);
        #pragma unroll
        for (int it = 0; it < 4; it++) {
            int idx = tid + it * 256;
            int r = idx >> 3, c = (idx & 7) * 4;
            asm volatile("cp.async.cg.shared.global [%0], [%1], 16;"
                         :: "r"(ab + (r * CBKPAD + c) * 4),
                            "l"(wOut + (size_t)r * 384 + ch * CBK + c));
        }
        const int m_base = (ch * CBK) / 3;
        uint32_t bb = smem_u32(&Bstg[buf][0]);
        #pragma unroll
        for (int it = 0; it < 2; it++) {
            int idx = tid + it * 256;
            if (idx < SROWS * 34) {
                int r = idx / 34, c4 = idx - r * 34;
                int mr = m_base + r;
                int t = t0 - 4 + c4 * 4;
                int tc = t < 0 ? 0 : (t > T_ - 4 ? T_ - 4 : t);
                int sz = (mr < 128 && t >= 0 && t <= T_ - 4) ? 16 : 0;
                int mrc = mr < 128 ? mr : 127;
                const float* src = Ab + (size_t)mrc * T_ + tc;
                asm volatile("cp.async.cg.shared.global [%0], [%1], 16, %2;"
                             :: "r"(bb + (r * SPAD + c4 * 4) * 4), "l"(src), "r"(sz));
            }
        }
        asm volatile("cp.async.commit_group;");
    };

    const int m_warp = (wid & 1) * 64;
    const int n_warp = (wid >> 1) * 32;

    float acc[4][4][4];
    #pragma unroll
    for (int mi = 0; mi < 4; mi++)
        #pragma unroll
        for (int nb = 0; nb < 4; nb++)
            #pragma unroll
            for (int e = 0; e < 4; e++) acc[mi][nb][e] = 0.f;

    const int a_row  = (lane < 16) ? lane : (lane - 16);
    const int a_koff = (lane < 16) ? 0 : 4;
    const int b_k    = lane & 3;
    const int b_n    = lane >> 2;

    const uint32_t As0 = smem_u32(&As[0][0]);

    load_chunk(0);

    for (int ch = 0; ch < 12; ch++) {
        if (ch < 11) {
            load_chunk(ch + 1);
            asm volatile("cp.async.wait_group 1;");
        } else {
            asm volatile("cp.async.wait_group 0;");
        }
        __syncthreads();

        const int buf = ch & 1;
        const int m_base = (ch * CBK) / 3;
        const uint32_t Asb = As0 + buf * (128 * CBKPAD * 4);
        const float*   stg = &Bstg[buf][0];

        #pragma unroll
        for (int ks = 0; ks < 4; ks++) {
            const int k0 = ks * 8;
            uint32_t ar[4][4];
            #pragma unroll
            for (int mi = 0; mi < 4; mi++) {
                uint32_t addr = Asb +
                    ((m_warp + mi * 16 + a_row) * CBKPAD + k0 + a_koff) * 4;
                LDSM4(ar[mi], addr);
            }
            const int kg0 = ch * CBK + k0 + b_k;
            const int kg1 = kg0 + 4;
            const int mr0 = kg0 / 3, kt0 = kg0 - mr0 * 3;
            const int mr1 = kg1 / 3, kt1 = kg1 - mr1 * 3;
            const float* row0 = stg + (mr0 - m_base) * SPAD + 3 + kt0;
            const float* row1 = stg + (mr1 - m_base) * SPAD + 3 + kt1;
            #pragma unroll
            for (int nb = 0; nb < 4; nb++) {
                const int n = n_warp + nb * 8 + b_n;
                uint32_t b0 = __float_as_uint(to_tf32(row0[n]));
                uint32_t b1 = __float_as_uint(to_tf32(row1[n]));
                #pragma unroll
                for (int mi = 0; mi < 4; mi++)
                    mma_tf32(acc[mi][nb], ar[mi], b0, b1);
            }
        }
        __syncthreads();
    }

    const int rg = lane >> 2;
    const int cg = (lane & 3) * 2;
    #pragma unroll
    for (int mi = 0; mi < 4; mi++) {
        const int row = m_warp + mi * 16 + rg;
        const float bi0 = __ldg(&bOut[row]);
        const float bi1 = __ldg(&bOut[row + 8]);
        float* r0 = out + ((size_t)b * 128 + row)     * T_ + t0;
        float* r1 = out + ((size_t)b * 128 + row + 8) * T_ + t0;
        #pragma unroll
        for (int nb = 0; nb < 4; nb++) {
            const int col = n_warp + nb * 8 + cg;
            const float* c = acc[mi][nb];
            *(float2*)(r0 + col) = make_float2(c[0] + bi0, c[1] + bi0);
            *(float2*)(r1 + col) = make_float2(c[2] + bi1, c[3] + bi1);
        }
    }
}

// =====================================================================
// launcher
// =====================================================================
extern "C" void kernel_launch(void* const* d_in, const int* in_sizes, int n_in,
                              void* d_out, int out_size)
{
    (void)in_sizes; (void)n_in; (void)out_size;
    const float* x    = (const float*)d_in[0];
    const float* cond = (const float*)d_in[1];
    const float* mask = (const float*)d_in[2];
    const float* wQ   = (const float*)d_in[3];
    const float* bQ   = (const float*)d_in[4];
    const float* wKV  = (const float*)d_in[5];
    const float* bKV  = (const float*)d_in[6];
    const float* wOut = (const float*)d_in[7];
    const float* bOut = (const float*)d_in[8];
    float* out = (float*)d_out;

    const size_t smQ  = (size_t)(32 * CAPAD + 32 * SPAD2) * sizeof(float);   // ~59 KB
    const size_t smKV = (size_t)(64 * CAPAD + 32 * SPAD2) * sizeof(float);   // ~81 KB
    const size_t smG  = (size_t)GSTAGES * STG2 * sizeof(uint16_t);           // 110592 B
    cudaFuncSetAttribute(kConv<32, true>,
                         cudaFuncAttributeMaxDynamicSharedMemorySize, (int)smQ);
    cudaFuncSetAttribute(kConv<64, false>,
                         cudaFuncAttributeMaxDynamicSharedMemorySize, (int)smKV);
    cudaFuncSetAttribute(kGemmMMA<2048, 1024, 0>,
                         cudaFuncAttributeMaxDynamicSharedMemorySize, (int)smG);
    cudaFuncSetAttribute(kGemmMMA<1024, 2048, 1>,
                         cudaFuncAttributeMaxDynamicSharedMemorySize, (int)smG);

    kConv<32, true ><<<dim3(T_ / 256, 4, B_), 256, smQ >>>(cond, wQ,  bQ,  nullptr);
    kConv<64, false><<<dim3(T_ / 256, 4, B_), 256, smKV>>>(x,    wKV, bKV, mask);
    // fused softmax: blocks [0,W) -> Q rows, [W, W+CP) -> K rows
    kSoftAll<<<dim3(W_ + CP_, B_), 256>>>();
    // GEMM1: D1[i][j] = sum_w vth[i][w] * kth[j][w]  (M=1024, N=1024, K=2048)
    kGemmMMA<2048, 1024, 0><<<dim3(CP_ / 128, CP_ / 128, B_), 256, smG>>>();
    // GEMM2: D2[w][i] = sum_j qh[w][j] * kvh[i][j]   (M=2048, N=1024, K=1024)
    kGemmMMA<1024, 2048, 1><<<dim3(CP_ / 128, W_ / 128, B_), 256, smG>>>();
    kConvMMA<<<dim3(T_ / 128, B_), 256>>>(wOut, bOut, out);
}